// round 5
// baseline (speedup 1.0000x reference)
#include <cuda_runtime.h>
#include <cuda_fp16.h>
#include <cstdint>
#include <cstddef>

#define DEVINL __device__ __forceinline__
using u32 = uint32_t;
using ull = unsigned long long;

constexpr int D  = 512;
constexpr int NC = 128;

constexpr int TILE_B   = 16384;            // one 128-row x 128B tile (hi+lo packed per row)
constexpr int STAGE_B  = 2 * TILE_B;       // A tile + B tile
constexpr int NSTAGE   = 3;
constexpr int MAIN_SMEM = NSTAGE * STAGE_B;          // 98304
constexpr int VQ_SMEM   = MAIN_SMEM + 512 + 4096 + 512;
constexpr int ZROW = 132;                  // padded fp32 row stride (floats) for epilogue staging

__device__ float g_cnorm[NC];
// pre-split operand tiles, exact smem layout (swizzled rows, hi|lo chunks)
__device__ __align__(128) char g_xsplit[256][16][TILE_B];   // 64 MB
__device__ __align__(128) char g_zsplit[256][16][TILE_B];   // 64 MB
__device__ __align__(128) char g_wsplit[4][16][TILE_B];     // 1 MB
__device__ __align__(128) char g_cbsplit[16][TILE_B];       // 256 KB

// ---------------------------------------------------------------- helpers
DEVINL u32 smem_u32(const void* p) {
    u32 a;
    asm("{ .reg .u64 t; cvta.to.shared.u64 t, %1; cvt.u32.u64 %0, t; }"
        : "=r"(a) : "l"(p));
    return a;
}
DEVINL void ldsm4(u32& r0, u32& r1, u32& r2, u32& r3, u32 a) {
    asm volatile("ldmatrix.sync.aligned.m8n8.x4.shared.b16 {%0,%1,%2,%3}, [%4];"
                 : "=r"(r0), "=r"(r1), "=r"(r2), "=r"(r3) : "r"(a));
}
DEVINL void mma_f16(float c[4], const u32 a[4], const u32 b[2]) {
    asm volatile(
        "mma.sync.aligned.m16n8k16.row.col.f32.f16.f16.f32 "
        "{%0,%1,%2,%3},{%4,%5,%6,%7},{%8,%9},{%0,%1,%2,%3};"
        : "+f"(c[0]), "+f"(c[1]), "+f"(c[2]), "+f"(c[3])
        : "r"(a[0]), "r"(a[1]), "r"(a[2]), "r"(a[3]), "r"(b[0]), "r"(b[1]));
}
DEVINL u32 pack_h2(__half a, __half b) {
    __half2 h = __halves2half2(a, b);
    return *reinterpret_cast<u32*>(&h);
}
DEVINL void fsplit(float x, __half& h, __half& l) {
    h = __float2half_rn(x);
    l = __float2half_rn(x - __half2float(h));
}
DEVINL void cp16(u32 dst, const void* src) {
    asm volatile("cp.async.cg.shared.global [%0], [%1], 16;" :: "r"(dst), "l"(src));
}
DEVINL void cp_commit() { asm volatile("cp.async.commit_group;" ::: "memory"); }
DEVINL void cp_wait1()  { asm volatile("cp.async.wait_group 1;" ::: "memory"); }
DEVINL void cp_wait0()  { asm volatile("cp.async.wait_group 0;" ::: "memory"); }

// split 16 fp32 (v[0..3]) into 2 hi + 2 lo 16B chunks of a packed tile row.
// hi chunk c stored at byte ((c^e)<<4), lo chunk c at (((c^4)^e)<<4), e=row&7.
DEVINL void split16(const float4 v[4], char* drow, int c0, int e) {
    #pragma unroll
    for (int c2 = 0; c2 < 2; ++c2) {
        const float f[8] = { v[2*c2].x, v[2*c2].y, v[2*c2].z, v[2*c2].w,
                             v[2*c2+1].x, v[2*c2+1].y, v[2*c2+1].z, v[2*c2+1].w };
        __half hh[8], ll[8];
        #pragma unroll
        for (int j = 0; j < 8; ++j) fsplit(f[j], hh[j], ll[j]);
        uint4 uh = make_uint4(pack_h2(hh[0], hh[1]), pack_h2(hh[2], hh[3]),
                              pack_h2(hh[4], hh[5]), pack_h2(hh[6], hh[7]));
        uint4 ul = make_uint4(pack_h2(ll[0], ll[1]), pack_h2(ll[2], ll[3]),
                              pack_h2(ll[4], ll[5]), pack_h2(ll[6], ll[7]));
        const int c = c0 + c2;
        *(uint4*)(drow + (((c)     ^ e) << 4)) = uh;
        *(uint4*)(drow + (((c ^ 4) ^ e) << 4)) = ul;
    }
}

// ---------------------------------------------------------------- prepass kernels
__global__ void split_x_kernel(const float* __restrict__ X) {
    const int s = blockIdx.x, rb = blockIdx.y;
    const int tid = threadIdx.x, r = tid >> 1, h = tid & 1;
    const float4* src = (const float4*)(X + (size_t)(rb * 128 + r) * D + s * 32 + h * 16);
    float4 v[4];
    #pragma unroll
    for (int i = 0; i < 4; ++i) v[i] = src[i];
    split16(v, &g_xsplit[rb][s][r * 128], h * 2, r & 7);
}

__global__ void split_const_kernel(const float* __restrict__ W,
                                   const float* __restrict__ CB) {
    const int b = blockIdx.x;
    const int tid = threadIdx.x, r = tid >> 1, h = tid & 1;
    if (b < 64) {
        const int ct = b >> 4, s = b & 15;
        const float4* src = (const float4*)(W + (size_t)(ct * 128 + r) * D + s * 32 + h * 16);
        float4 v[4];
        #pragma unroll
        for (int i = 0; i < 4; ++i) v[i] = src[i];
        split16(v, &g_wsplit[ct][s][r * 128], h * 2, r & 7);
    } else if (b < 80) {
        const int s = b - 64;
        const float4* src = (const float4*)(CB + (size_t)r * D + s * 32 + h * 16);
        float4 v[4];
        #pragma unroll
        for (int i = 0; i < 4; ++i) v[i] = src[i];
        split16(v, &g_cbsplit[s][r * 128], h * 2, r & 7);
    } else {
        const int c = tid >> 1;
        const float4* p = (const float4*)(CB + (size_t)c * D + h * 256);
        float s = 0.f;
        #pragma unroll 4
        for (int k = 0; k < 64; ++k) {
            float4 v = p[k];
            s += v.x * v.x + v.y * v.y + v.z * v.z + v.w * v.w;
        }
        s += __shfl_xor_sync(0xffffffffu, s, 1);
        if (!h) g_cnorm[c] = s;
    }
}

// ---------------------------------------------------------------- per-stage MMA (128x128x32, split-2)
DEVINL void stage_mma(u32 aT, int tid, float acc[4][4][4]) {
    const int lane = tid & 31, w = tid >> 5;
    const int mw = w >> 2, nw = w & 3;
    const int eL = lane & 7;
    const int rA = lane & 15, cAk = lane >> 4;
    const int rB0 = nw * 32 + ((lane >> 4) << 3) + (lane & 7);
    const int cBk = (lane >> 3) & 1;
    const u32 bT = aT + TILE_B;

    #pragma unroll
    for (int kk = 0; kk < 2; ++kk) {
        u32 ahi[4][4], alo[4][4], bhi[4][2], blo[4][2];
        const int swA = (kk * 2 + cAk) ^ eL;
        #pragma unroll
        for (int mb = 0; mb < 4; ++mb) {
            const u32 base = aT + (mw * 64 + mb * 16 + rA) * 128;
            ldsm4(ahi[mb][0], ahi[mb][1], ahi[mb][2], ahi[mb][3], base + (swA << 4));
            ldsm4(alo[mb][0], alo[mb][1], alo[mb][2], alo[mb][3], base + ((swA ^ 4) << 4));
        }
        const int swB = (kk * 2 + cBk) ^ eL;
        #pragma unroll
        for (int bp = 0; bp < 2; ++bp) {
            const u32 base = bT + (rB0 + bp * 16) * 128;
            u32 r0, r1, r2, r3;
            ldsm4(r0, r1, r2, r3, base + (swB << 4));
            bhi[bp*2][0] = r0; bhi[bp*2][1] = r1;
            bhi[bp*2+1][0] = r2; bhi[bp*2+1][1] = r3;
            ldsm4(r0, r1, r2, r3, base + ((swB ^ 4) << 4));
            blo[bp*2][0] = r0; blo[bp*2][1] = r1;
            blo[bp*2+1][0] = r2; blo[bp*2+1][1] = r3;
        }
        #pragma unroll
        for (int mb = 0; mb < 4; ++mb)
            #pragma unroll
            for (int nb = 0; nb < 4; ++nb) {
                mma_f16(acc[mb][nb], ahi[mb], bhi[nb]);
                mma_f16(acc[mb][nb], ahi[mb], blo[nb]);
                mma_f16(acc[mb][nb], alo[mb], bhi[nb]);
            }
    }
}

// ---------------------------------------------------------------- GEMM: Z = X W^T + b (+ split-z emit)
__global__ void __launch_bounds__(256, 2)
gemm_hmma(const float* __restrict__ bias, float* __restrict__ Z)
{
    extern __shared__ char smc[];
    const u32 sb = smem_u32(smc);
    const int tid = threadIdx.x;
    const int ct = blockIdx.x, rb = blockIdx.y;      // x = col tile (fast) -> L2 reuse of X
    const int r128 = tid & 127;

    const char* srcBase = (tid < 128) ? &g_xsplit[rb][0][0] : &g_wsplit[ct][0][0];
    const u32 dstOff = ((tid < 128) ? 0u : (u32)TILE_B) + r128 * 128;

    #define G_ISSUE(s, buf) do {                                              \
        const char* _src = srcBase + (s) * TILE_B + r128 * 128;               \
        const u32 _d = sb + (buf) * STAGE_B + dstOff;                         \
        _Pragma("unroll")                                                     \
        for (int _i = 0; _i < 8; ++_i) cp16(_d + _i * 16, _src + _i * 16);    \
    } while (0)

    G_ISSUE(0, 0); cp_commit();
    G_ISSUE(1, 1); cp_commit();

    float acc[4][4][4] = {};
    int buf = 0;
    #pragma unroll 1
    for (int s = 0; s < 16; ++s) {
        cp_wait1();
        __syncthreads();
        int b2 = buf + 2; if (b2 >= 3) b2 -= 3;
        if (s + 2 < 16) G_ISSUE(s + 2, b2);
        cp_commit();
        stage_mma(sb + buf * STAGE_B, tid, acc);
        if (++buf == 3) buf = 0;
    }
    #undef G_ISSUE

    // ---- epilogue: stage z tile in smem, write Z fp32 coalesced + emit split tiles
    cp_wait0();
    __syncthreads();

    float* zs = (float*)smc;                          // [128][ZROW]
    const int lane = tid & 31, w = tid >> 5;
    const int mw = w >> 2, nw = w & 3;
    const int row0 = rb * 128, col0 = ct * 128;

    #pragma unroll
    for (int nb = 0; nb < 4; ++nb) {
        const int cb = nw * 32 + nb * 8 + (lane & 3) * 2;
        const float2 bv = *(const float2*)&bias[col0 + cb];
        #pragma unroll
        for (int mb = 0; mb < 4; ++mb) {
            const int rr = mw * 64 + mb * 16 + (lane >> 2);
            *(float2*)&zs[rr * ZROW + cb] =
                make_float2(acc[mb][nb][0] + bv.x, acc[mb][nb][1] + bv.y);
            *(float2*)&zs[(rr + 8) * ZROW + cb] =
                make_float2(acc[mb][nb][2] + bv.x, acc[mb][nb][3] + bv.y);
        }
    }
    __syncthreads();

    // coalesced fp32 Z store
    #pragma unroll
    for (int it = 0; it < 16; ++it) {
        const int idx = tid + it * 256;               // 4096 float4 slots
        const int rr = idx >> 5, c4 = (idx & 31) * 4;
        float4 v = *(float4*)&zs[rr * ZROW + c4];
        *(float4*)&Z[(size_t)(row0 + rr) * D + col0 + c4] = v;
    }

    // split-z emit (same layout as g_xsplit)
    const int r = tid >> 1, h = tid & 1, e = r & 7;
    #pragma unroll
    for (int sl = 0; sl < 4; ++sl) {
        float4 v[4];
        #pragma unroll
        for (int i = 0; i < 4; ++i) v[i] = *(float4*)&zs[r * ZROW + sl * 32 + h * 16 + i * 4];
        split16(v, &g_zsplit[rb][ct * 4 + sl][r * 128], h * 2, e);
    }
}

// ---------------------------------------------------------------- VQ: dots, argmin, gather (pure cp.async)
__global__ void __launch_bounds__(256, 2)
vq_hmma(const float* __restrict__ CB, float* __restrict__ Q1, float* __restrict__ Q2)
{
    extern __shared__ char smc[];
    float* scn  = (float*)(smc + MAIN_SMEM);
    ull*   wb   = (ull*)  (smc + MAIN_SMEM + 512);
    int*   bidx = (int*)  (smc + MAIN_SMEM + 512 + 4096);

    const u32 sb = smem_u32(smc);
    const int tid = threadIdx.x;
    const int rb = blockIdx.x;
    const int row0 = rb * 128;
    if (tid < NC) scn[tid] = g_cnorm[tid];

    const int r128 = tid & 127;
    const char* srcBase = (tid < 128) ? &g_zsplit[rb][0][0] : &g_cbsplit[0][0];
    const u32 dstOff = ((tid < 128) ? 0u : (u32)TILE_B) + r128 * 128;

    #define V_ISSUE(s, buf) do {                                              \
        const char* _src = srcBase + (s) * TILE_B + r128 * 128;               \
        const u32 _d = sb + (buf) * STAGE_B + dstOff;                         \
        _Pragma("unroll")                                                     \
        for (int _i = 0; _i < 8; ++_i) cp16(_d + _i * 16, _src + _i * 16);    \
    } while (0)

    V_ISSUE(0, 0); cp_commit();
    V_ISSUE(1, 1); cp_commit();

    float acc[4][4][4] = {};
    int buf = 0;
    #pragma unroll 1
    for (int s = 0; s < 16; ++s) {
        cp_wait1();
        __syncthreads();
        int b2 = buf + 2; if (b2 >= 3) b2 -= 3;
        if (s + 2 < 16) V_ISSUE(s + 2, b2);
        cp_commit();
        stage_mma(sb + buf * STAGE_B, tid, acc);
        if (++buf == 3) buf = 0;
    }
    #undef V_ISSUE

    const int lane = tid & 31, w = tid >> 5;
    const int mw = w >> 2, nw = w & 3;

    #pragma unroll
    for (int mb = 0; mb < 4; ++mb) {
        #pragma unroll
        for (int rh = 0; rh < 2; ++rh) {
            ull best = ~0ull;
            #pragma unroll
            for (int nb = 0; nb < 4; ++nb) {
                #pragma unroll
                for (int j = 0; j < 2; ++j) {
                    const int code = nw * 32 + nb * 8 + (lane & 3) * 2 + j;
                    const float sc = fmaf(-2.f, acc[mb][nb][rh * 2 + j], scn[code]);
                    u32 o = __float_as_uint(sc);
                    o = (o & 0x80000000u) ? ~o : (o | 0x80000000u);
                    const ull key = ((ull)o << 32) | (u32)code;
                    if (key < best) best = key;
                }
            }
            ull t = __shfl_xor_sync(0xffffffffu, best, 1); if (t < best) best = t;
            t     = __shfl_xor_sync(0xffffffffu, best, 2); if (t < best) best = t;
            const int rowl = mw * 64 + mb * 16 + rh * 8 + (lane >> 2);
            if ((lane & 3) == 0) wb[rowl * 4 + nw] = best;
        }
    }
    __syncthreads();

    if (tid < 128) {
        ull m = wb[tid * 4];
        ull a = wb[tid * 4 + 1]; if (a < m) m = a;
        a = wb[tid * 4 + 2];     if (a < m) m = a;
        a = wb[tid * 4 + 3];     if (a < m) m = a;
        bidx[tid] = (int)(m & 0xffffffffu);
    }
    __syncthreads();

    for (int rr = w; rr < 128; rr += 8) {
        const int idx = bidx[rr];
        const float4* s4 = (const float4*)(CB + (size_t)idx * D);
        float4* o1 = (float4*)(Q1 + (size_t)(row0 + rr) * D);
        float4* o2 = (float4*)(Q2 + (size_t)(row0 + rr) * D);
        #pragma unroll
        for (int i = lane; i < D / 4; i += 32) {
            const float4 vv = s4[i];
            o1[i] = vv;
            o2[i] = vv;
        }
    }
}

// ---------------------------------------------------------------- launcher
extern "C" void kernel_launch(void* const* d_in, const int* in_sizes, int n_in,
                              void* d_out, int out_size)
{
    const float* x  = (const float*)d_in[0];
    const float* W  = (const float*)d_in[1];
    const float* b  = (const float*)d_in[2];
    const float* cb = (const float*)d_in[3];

    const int M = in_sizes[0] / D;            // 32768

    float* out = (float*)d_out;
    float* q1 = out;
    float* q2 = out + (size_t)M * D;
    float* z  = out + (size_t)2 * M * D;

    split_const_kernel<<<81, 256>>>(W, cb);
    split_x_kernel<<<dim3(16, M / 128), 256>>>(x);

    cudaFuncSetAttribute(gemm_hmma, cudaFuncAttributeMaxDynamicSharedMemorySize, MAIN_SMEM);
    gemm_hmma<<<dim3(D / 128, M / 128), 256, MAIN_SMEM>>>(b, z);

    cudaFuncSetAttribute(vq_hmma, cudaFuncAttributeMaxDynamicSharedMemorySize, VQ_SMEM);
    vq_hmma<<<M / 128, 256, VQ_SMEM>>>(cb, q1, q2);
}

// round 6
// speedup vs baseline: 1.4904x; 1.4904x over previous
#include <cuda_runtime.h>
#include <cuda_fp16.h>
#include <cstdint>
#include <cstddef>

#define DEVINL __device__ __forceinline__
using u32 = uint32_t;
using ull = unsigned long long;

constexpr int D  = 512;
constexpr int NC = 128;

constexpr int TILE_B   = 16384;            // one 128-row x 128B tile (hi+lo packed per row)
constexpr int STAGE_B  = 2 * TILE_B;       // A tile + B tile
constexpr int NSTAGE   = 3;
constexpr int MAIN_SMEM = NSTAGE * STAGE_B;          // 98304
constexpr int VQ_SMEM   = MAIN_SMEM + 512 + 4096 + 512;
constexpr int ZROW = 132;                  // padded fp32 row stride (floats) for epilogue staging

__device__ float g_cnorm[NC];
// pre-split operand tiles, exact smem layout (swizzled rows, hi|lo chunks)
__device__ __align__(128) char g_xsplit[256][16][TILE_B];   // 64 MB
__device__ __align__(128) char g_zsplit[256][16][TILE_B];   // 64 MB
__device__ __align__(128) char g_wsplit[4][16][TILE_B];     // 1 MB
__device__ __align__(128) char g_cbsplit[16][TILE_B];       // 256 KB

// ---------------------------------------------------------------- helpers
DEVINL u32 smem_u32(const void* p) {
    u32 a;
    asm("{ .reg .u64 t; cvta.to.shared.u64 t, %1; cvt.u32.u64 %0, t; }"
        : "=r"(a) : "l"(p));
    return a;
}
DEVINL void ldsm4(u32& r0, u32& r1, u32& r2, u32& r3, u32 a) {
    asm volatile("ldmatrix.sync.aligned.m8n8.x4.shared.b16 {%0,%1,%2,%3}, [%4];"
                 : "=r"(r0), "=r"(r1), "=r"(r2), "=r"(r3) : "r"(a));
}
DEVINL void mma_f16(float c[4], const u32 a[4], const u32 b[2]) {
    asm volatile(
        "mma.sync.aligned.m16n8k16.row.col.f32.f16.f16.f32 "
        "{%0,%1,%2,%3},{%4,%5,%6,%7},{%8,%9},{%0,%1,%2,%3};"
        : "+f"(c[0]), "+f"(c[1]), "+f"(c[2]), "+f"(c[3])
        : "r"(a[0]), "r"(a[1]), "r"(a[2]), "r"(a[3]), "r"(b[0]), "r"(b[1]));
}
DEVINL u32 pack_h2(__half a, __half b) {
    __half2 h = __halves2half2(a, b);
    return *reinterpret_cast<u32*>(&h);
}
DEVINL void fsplit(float x, __half& h, __half& l) {
    h = __float2half_rn(x);
    l = __float2half_rn(x - __half2float(h));
}
DEVINL void cp16(u32 dst, const void* src) {
    asm volatile("cp.async.cg.shared.global [%0], [%1], 16;" :: "r"(dst), "l"(src));
}
DEVINL void cp_commit() { asm volatile("cp.async.commit_group;" ::: "memory"); }
DEVINL void cp_wait1()  { asm volatile("cp.async.wait_group 1;" ::: "memory"); }
DEVINL void cp_wait0()  { asm volatile("cp.async.wait_group 0;" ::: "memory"); }

// split 16 fp32 (v[0..3]) into 2 hi + 2 lo 16B chunks of a packed tile row.
// hi chunk c stored at byte ((c^e)<<4), lo chunk c at (((c^4)^e)<<4), e=row&7.
DEVINL void split16(const float4 v[4], char* drow, int c0, int e) {
    #pragma unroll
    for (int c2 = 0; c2 < 2; ++c2) {
        const float f[8] = { v[2*c2].x, v[2*c2].y, v[2*c2].z, v[2*c2].w,
                             v[2*c2+1].x, v[2*c2+1].y, v[2*c2+1].z, v[2*c2+1].w };
        __half hh[8], ll[8];
        #pragma unroll
        for (int j = 0; j < 8; ++j) fsplit(f[j], hh[j], ll[j]);
        uint4 uh = make_uint4(pack_h2(hh[0], hh[1]), pack_h2(hh[2], hh[3]),
                              pack_h2(hh[4], hh[5]), pack_h2(hh[6], hh[7]));
        uint4 ul = make_uint4(pack_h2(ll[0], ll[1]), pack_h2(ll[2], ll[3]),
                              pack_h2(ll[4], ll[5]), pack_h2(ll[6], ll[7]));
        const int c = c0 + c2;
        *(uint4*)(drow + (((c)     ^ e) << 4)) = uh;
        *(uint4*)(drow + (((c ^ 4) ^ e) << 4)) = ul;
    }
}

// ---------------------------------------------------------------- prepass kernels
// stage split tile in smem, then write out linearly (coalesced, conflict-free)
__global__ void split_x_kernel(const float* __restrict__ X) {
    __shared__ __align__(16) char st[TILE_B];
    const int s = blockIdx.x, rb = blockIdx.y;
    const int tid = threadIdx.x, r = tid >> 1, h = tid & 1;
    const float4* src = (const float4*)(X + (size_t)(rb * 128 + r) * D + s * 32 + h * 16);
    float4 v[4];
    #pragma unroll
    for (int i = 0; i < 4; ++i) v[i] = src[i];
    split16(v, &st[r * 128], h * 2, r & 7);
    __syncthreads();
    char* dst = &g_xsplit[rb][s][0];
    #pragma unroll
    for (int k = 0; k < 4; ++k)
        *(uint4*)(dst + tid * 16 + k * 4096) = *(const uint4*)(st + tid * 16 + k * 4096);
}

__global__ void split_const_kernel(const float* __restrict__ W,
                                   const float* __restrict__ CB) {
    __shared__ __align__(16) char st[TILE_B];
    const int b = blockIdx.x;
    const int tid = threadIdx.x, r = tid >> 1, h = tid & 1;
    if (b < 80) {
        const float* src0;
        char* dst;
        if (b < 64) {
            const int ct = b >> 4, s = b & 15;
            src0 = W + (size_t)(ct * 128 + r) * D + s * 32 + h * 16;
            dst = &g_wsplit[ct][s][0];
        } else {
            const int s = b - 64;
            src0 = CB + (size_t)r * D + s * 32 + h * 16;
            dst = &g_cbsplit[s][0];
        }
        float4 v[4];
        #pragma unroll
        for (int i = 0; i < 4; ++i) v[i] = ((const float4*)src0)[i];
        split16(v, &st[r * 128], h * 2, r & 7);
        __syncthreads();
        #pragma unroll
        for (int k = 0; k < 4; ++k)
            *(uint4*)(dst + tid * 16 + k * 4096) = *(const uint4*)(st + tid * 16 + k * 4096);
    } else {
        const int c = tid >> 1;
        const float4* p = (const float4*)(CB + (size_t)c * D + h * 256);
        float s = 0.f;
        #pragma unroll 4
        for (int k = 0; k < 64; ++k) {
            float4 v = p[k];
            s += v.x * v.x + v.y * v.y + v.z * v.z + v.w * v.w;
        }
        s += __shfl_xor_sync(0xffffffffu, s, 1);
        if (!h) g_cnorm[c] = s;
    }
}

// ---------------------------------------------------------------- per-stage MMA (128x128x32, split-2)
DEVINL void stage_mma(u32 aT, int tid, float acc[4][4][4]) {
    const int lane = tid & 31, w = tid >> 5;
    const int mw = w >> 2, nw = w & 3;
    const int eL = lane & 7;
    const int rA = lane & 15, cAk = lane >> 4;
    const int rB0 = nw * 32 + ((lane >> 4) << 3) + (lane & 7);
    const int cBk = (lane >> 3) & 1;
    const u32 bT = aT + TILE_B;

    #pragma unroll
    for (int kk = 0; kk < 2; ++kk) {
        u32 ahi[4][4], alo[4][4], bhi[4][2], blo[4][2];
        const int swA = (kk * 2 + cAk) ^ eL;
        #pragma unroll
        for (int mb = 0; mb < 4; ++mb) {
            const u32 base = aT + (mw * 64 + mb * 16 + rA) * 128;
            ldsm4(ahi[mb][0], ahi[mb][1], ahi[mb][2], ahi[mb][3], base + (swA << 4));
            ldsm4(alo[mb][0], alo[mb][1], alo[mb][2], alo[mb][3], base + ((swA ^ 4) << 4));
        }
        const int swB = (kk * 2 + cBk) ^ eL;
        #pragma unroll
        for (int bp = 0; bp < 2; ++bp) {
            const u32 base = bT + (rB0 + bp * 16) * 128;
            u32 r0, r1, r2, r3;
            ldsm4(r0, r1, r2, r3, base + (swB << 4));
            bhi[bp*2][0] = r0; bhi[bp*2][1] = r1;
            bhi[bp*2+1][0] = r2; bhi[bp*2+1][1] = r3;
            ldsm4(r0, r1, r2, r3, base + ((swB ^ 4) << 4));
            blo[bp*2][0] = r0; blo[bp*2][1] = r1;
            blo[bp*2+1][0] = r2; blo[bp*2+1][1] = r3;
        }
        #pragma unroll
        for (int mb = 0; mb < 4; ++mb)
            #pragma unroll
            for (int nb = 0; nb < 4; ++nb) {
                mma_f16(acc[mb][nb], ahi[mb], bhi[nb]);
                mma_f16(acc[mb][nb], ahi[mb], blo[nb]);
                mma_f16(acc[mb][nb], alo[mb], bhi[nb]);
            }
    }
}

// ---------------------------------------------------------------- GEMM: Z = X W^T + b (+ split-z emit)
__global__ void __launch_bounds__(256, 2)
gemm_hmma(const float* __restrict__ bias, float* __restrict__ Z)
{
    extern __shared__ char smc[];
    const u32 sb = smem_u32(smc);
    const int tid = threadIdx.x;
    const int ct = blockIdx.x, rb = blockIdx.y;      // x = col tile (fast) -> L2 reuse of X
    const int li = tid & 127;

    // linear conflict-free copy: thread li copies 16B at li*16 + k*2048 of the 16KB tile
    const char* srcBase = (tid < 128) ? &g_xsplit[rb][0][0] : &g_wsplit[ct][0][0];
    const u32 dstBase = ((tid < 128) ? 0u : (u32)TILE_B) + li * 16;

    #define G_ISSUE(s, buf) do {                                              \
        const char* _src = srcBase + (s) * TILE_B + li * 16;                  \
        const u32 _d = sb + (buf) * STAGE_B + dstBase;                        \
        _Pragma("unroll")                                                     \
        for (int _k = 0; _k < 8; ++_k) cp16(_d + _k * 2048, _src + _k * 2048);\
    } while (0)

    G_ISSUE(0, 0); cp_commit();
    G_ISSUE(1, 1); cp_commit();

    float acc[4][4][4] = {};
    int buf = 0;
    #pragma unroll 1
    for (int s = 0; s < 16; ++s) {
        cp_wait1();
        __syncthreads();
        int b2 = buf + 2; if (b2 >= 3) b2 -= 3;
        if (s + 2 < 16) G_ISSUE(s + 2, b2);
        cp_commit();
        stage_mma(sb + buf * STAGE_B, tid, acc);
        if (++buf == 3) buf = 0;
    }
    #undef G_ISSUE

    // ---- epilogue: stage z tile in smem, write Z fp32 coalesced + emit split tiles
    cp_wait0();
    __syncthreads();

    float* zs = (float*)smc;                          // [128][ZROW] = 67584 B
    char*  scr = smc + 128 * ZROW * 4;                // 16KB scratch (fits in 98304)
    const int lane = tid & 31, w = tid >> 5;
    const int mw = w >> 2, nw = w & 3;
    const int row0 = rb * 128, col0 = ct * 128;

    #pragma unroll
    for (int nb = 0; nb < 4; ++nb) {
        const int cb = nw * 32 + nb * 8 + (lane & 3) * 2;
        const float2 bv = *(const float2*)&bias[col0 + cb];
        #pragma unroll
        for (int mb = 0; mb < 4; ++mb) {
            const int rr = mw * 64 + mb * 16 + (lane >> 2);
            *(float2*)&zs[rr * ZROW + cb] =
                make_float2(acc[mb][nb][0] + bv.x, acc[mb][nb][1] + bv.y);
            *(float2*)&zs[(rr + 8) * ZROW + cb] =
                make_float2(acc[mb][nb][2] + bv.x, acc[mb][nb][3] + bv.y);
        }
    }
    __syncthreads();

    // coalesced fp32 Z store
    #pragma unroll
    for (int it = 0; it < 16; ++it) {
        const int idx = tid + it * 256;               // 4096 float4 slots
        const int rr = idx >> 5, c4 = (idx & 31) * 4;
        float4 v = *(float4*)&zs[rr * ZROW + c4];
        *(float4*)&Z[(size_t)(row0 + rr) * D + col0 + c4] = v;
    }

    // split-z emit: convert slice into scratch, then linear coalesced STG
    const int r = tid >> 1, h = tid & 1, e = r & 7;
    #pragma unroll 1
    for (int sl = 0; sl < 4; ++sl) {
        float4 v[4];
        #pragma unroll
        for (int i = 0; i < 4; ++i) v[i] = *(float4*)&zs[r * ZROW + sl * 32 + h * 16 + i * 4];
        split16(v, scr + r * 128, h * 2, e);
        __syncthreads();
        char* dst = &g_zsplit[rb][ct * 4 + sl][0];
        #pragma unroll
        for (int k = 0; k < 4; ++k)
            *(uint4*)(dst + tid * 16 + k * 4096) = *(const uint4*)(scr + tid * 16 + k * 4096);
        __syncthreads();
    }
}

// ---------------------------------------------------------------- VQ: dots, argmin, gather (pure cp.async)
__global__ void __launch_bounds__(256, 2)
vq_hmma(const float* __restrict__ CB, float* __restrict__ Q1, float* __restrict__ Q2)
{
    extern __shared__ char smc[];
    float* scn  = (float*)(smc + MAIN_SMEM);
    ull*   wb   = (ull*)  (smc + MAIN_SMEM + 512);
    int*   bidx = (int*)  (smc + MAIN_SMEM + 512 + 4096);

    const u32 sb = smem_u32(smc);
    const int tid = threadIdx.x;
    const int rb = blockIdx.x;
    const int row0 = rb * 128;
    if (tid < NC) scn[tid] = g_cnorm[tid];

    const int li = tid & 127;
    const char* srcBase = (tid < 128) ? &g_zsplit[rb][0][0] : &g_cbsplit[0][0];
    const u32 dstBase = ((tid < 128) ? 0u : (u32)TILE_B) + li * 16;

    #define V_ISSUE(s, buf) do {                                              \
        const char* _src = srcBase + (s) * TILE_B + li * 16;                  \
        const u32 _d = sb + (buf) * STAGE_B + dstBase;                        \
        _Pragma("unroll")                                                     \
        for (int _k = 0; _k < 8; ++_k) cp16(_d + _k * 2048, _src + _k * 2048);\
    } while (0)

    V_ISSUE(0, 0); cp_commit();
    V_ISSUE(1, 1); cp_commit();

    float acc[4][4][4] = {};
    int buf = 0;
    #pragma unroll 1
    for (int s = 0; s < 16; ++s) {
        cp_wait1();
        __syncthreads();
        int b2 = buf + 2; if (b2 >= 3) b2 -= 3;
        if (s + 2 < 16) V_ISSUE(s + 2, b2);
        cp_commit();
        stage_mma(sb + buf * STAGE_B, tid, acc);
        if (++buf == 3) buf = 0;
    }
    #undef V_ISSUE

    const int lane = tid & 31, w = tid >> 5;
    const int mw = w >> 2, nw = w & 3;

    #pragma unroll
    for (int mb = 0; mb < 4; ++mb) {
        #pragma unroll
        for (int rh = 0; rh < 2; ++rh) {
            ull best = ~0ull;
            #pragma unroll
            for (int nb = 0; nb < 4; ++nb) {
                #pragma unroll
                for (int j = 0; j < 2; ++j) {
                    const int code = nw * 32 + nb * 8 + (lane & 3) * 2 + j;
                    const float sc = fmaf(-2.f, acc[mb][nb][rh * 2 + j], scn[code]);
                    u32 o = __float_as_uint(sc);
                    o = (o & 0x80000000u) ? ~o : (o | 0x80000000u);
                    const ull key = ((ull)o << 32) | (u32)code;
                    if (key < best) best = key;
                }
            }
            ull t = __shfl_xor_sync(0xffffffffu, best, 1); if (t < best) best = t;
            t     = __shfl_xor_sync(0xffffffffu, best, 2); if (t < best) best = t;
            const int rowl = mw * 64 + mb * 16 + rh * 8 + (lane >> 2);
            if ((lane & 3) == 0) wb[rowl * 4 + nw] = best;
        }
    }
    __syncthreads();

    if (tid < 128) {
        ull m = wb[tid * 4];
        ull a = wb[tid * 4 + 1]; if (a < m) m = a;
        a = wb[tid * 4 + 2];     if (a < m) m = a;
        a = wb[tid * 4 + 3];     if (a < m) m = a;
        bidx[tid] = (int)(m & 0xffffffffu);
    }
    __syncthreads();

    for (int rr = w; rr < 128; rr += 8) {
        const int idx = bidx[rr];
        const float4* s4 = (const float4*)(CB + (size_t)idx * D);
        float4* o1 = (float4*)(Q1 + (size_t)(row0 + rr) * D);
        float4* o2 = (float4*)(Q2 + (size_t)(row0 + rr) * D);
        #pragma unroll
        for (int i = lane; i < D / 4; i += 32) {
            const float4 vv = s4[i];
            o1[i] = vv;
            o2[i] = vv;
        }
    }
}

// ---------------------------------------------------------------- launcher
extern "C" void kernel_launch(void* const* d_in, const int* in_sizes, int n_in,
                              void* d_out, int out_size)
{
    const float* x  = (const float*)d_in[0];
    const float* W  = (const float*)d_in[1];
    const float* b  = (const float*)d_in[2];
    const float* cb = (const float*)d_in[3];

    const int M = in_sizes[0] / D;            // 32768

    float* out = (float*)d_out;
    float* q1 = out;
    float* q2 = out + (size_t)M * D;
    float* z  = out + (size_t)2 * M * D;

    split_const_kernel<<<81, 256>>>(W, cb);
    split_x_kernel<<<dim3(16, M / 128), 256>>>(x);

    cudaFuncSetAttribute(gemm_hmma, cudaFuncAttributeMaxDynamicSharedMemorySize, MAIN_SMEM);
    gemm_hmma<<<dim3(D / 128, M / 128), 256, MAIN_SMEM>>>(b, z);

    cudaFuncSetAttribute(vq_hmma, cudaFuncAttributeMaxDynamicSharedMemorySize, VQ_SMEM);
    vq_hmma<<<M / 128, 256, VQ_SMEM>>>(cb, q1, q2);
}